// round 1
// baseline (speedup 1.0000x reference)
#include <cuda_runtime.h>
#include <cuda_bf16.h>
#include <cstdint>

#define BATCH 8
#define NPTS  4096
#define DDIM  512
#define NT    32          // 4096 / 128 tiles per dim
#define PAIRS 528         // NT*(NT+1)/2
#define BK    32

// Scratch (no cudaMalloc allowed): bf16 x, per-point sq and 1/(1-sq)
__device__ __nv_bfloat16 g_xb[(size_t)BATCH * NPTS * DDIM];
__device__ float g_sq[BATCH * NPTS];
__device__ float g_inv[BATCH * NPTS];

// ---------------------------------------------------------------- prep ----
__global__ void prep_kernel(const float* __restrict__ emb) {
    int row = blockIdx.x;               // b*NPTS + n
    int tid = threadIdx.x;              // 128 threads
    const float* src = emb + (size_t)row * DDIM;

    float v[4];
    float s = 0.f;
#pragma unroll
    for (int i = 0; i < 4; ++i) {
        v[i] = src[tid + i * 128];
        s = fmaf(v[i], v[i], s);
    }
    __shared__ float red[4];
#pragma unroll
    for (int o = 16; o > 0; o >>= 1) s += __shfl_down_sync(0xffffffffu, s, o);
    if ((tid & 31) == 0) red[tid >> 5] = s;
    __syncthreads();
    float tot = red[0] + red[1] + red[2] + red[3];

    float nrm = sqrtf(tot);
    if (nrm >= 1.f) {                   // __proj (won't trigger for this data, but faithful)
        float invn = 1.f / nrm;
        float s2 = 0.f;
#pragma unroll
        for (int i = 0; i < 4; ++i) {
            v[i] = v[i] * invn - 1e-5f;
            s2 = fmaf(v[i], v[i], s2);
        }
#pragma unroll
        for (int o = 16; o > 0; o >>= 1) s2 += __shfl_down_sync(0xffffffffu, s2, o);
        __syncthreads();
        if ((tid & 31) == 0) red[tid >> 5] = s2;
        __syncthreads();
        tot = red[0] + red[1] + red[2] + red[3];
    }

#pragma unroll
    for (int i = 0; i < 4; ++i)
        g_xb[(size_t)row * DDIM + tid + i * 128] = __float2bfloat16(v[i]);
    if (tid == 0) {
        g_sq[row]  = tot;
        g_inv[row] = 1.f / (1.f - tot);
    }
}

// ------------------------------------------------------------- helpers ----
__device__ __forceinline__ void cp_async16(void* dst, const void* src) {
    uint32_t d = (uint32_t)__cvta_generic_to_shared(dst);
    asm volatile("cp.async.cg.shared.global [%0], [%1], 16;\n" :: "r"(d), "l"(src));
}
__device__ __forceinline__ void cp_commit() {
    asm volatile("cp.async.commit_group;\n" ::);
}
template <int N>
__device__ __forceinline__ void cp_wait() {
    asm volatile("cp.async.wait_group %0;\n" :: "n"(N));
}

__device__ __forceinline__ float hyp_dist(float gv, float sa, float sb,
                                          float ia, float ib, bool diag) {
    float d2 = fmaxf(sa + sb - 2.f * gv, 0.f);
    float dn;
    asm("sqrt.approx.f32 %0, %1;" : "=f"(dn) : "f"(d2));
    float t = 2.f * dn * ia * ib;           // arg = 1 + t
    float w;
    asm("sqrt.approx.f32 %0, %1;" : "=f"(w) : "f"(t * (t + 2.f)));  // sqrt(arg^2-1)
    float arg = 1.f + t + w;
    float lg;
    asm("lg2.approx.f32 %0, %1;" : "=f"(lg) : "f"(arg));
    return (t > 0.f && !diag) ? lg * 0.69314718055994531f : 0.f;
}

// ---------------------------------------------------------------- gemm ----
__global__ void __launch_bounds__(256, 2)
gram_dist_kernel(float* __restrict__ out) {
    __shared__ __align__(16) __nv_bfloat16 As[2][128][BK + 8];
    __shared__ __align__(16) __nv_bfloat16 Bs[2][128][BK + 8];
    __shared__ float s_sqi[128], s_invi[128], s_sqj[128], s_invj[128];

    const int b   = blockIdx.y;
    const int bN  = b * NPTS;

    // pair index -> (ti, tj), ti <= tj
    int p = blockIdx.x, ti = 0;
    while (p >= NT - ti) { p -= NT - ti; ++ti; }
    const int tj = ti + p;

    const int tid = threadIdx.x;
    const int warp = tid >> 5;
    const int lane = tid & 31;
    const int g  = lane >> 2;           // group id 0..7
    const int t2 = (lane & 3) * 2;      // 0,2,4,6
    const int wm = warp & 1;            // 2 m-blocks of 64
    const int wn = warp >> 1;           // 4 n-blocks of 32

    // per-row/col epilogue params
    if (tid < 128) {
        s_sqi[tid]  = g_sq[bN + ti * 128 + tid];
        s_invi[tid] = g_inv[bN + ti * 128 + tid];
    } else {
        int u = tid - 128;
        s_sqj[u]  = g_sq[bN + tj * 128 + u];
        s_invj[u] = g_inv[bN + tj * 128 + u];
    }

    // stage loader: 1024 16B chunks (A then B), 4 per thread
    auto load_stage = [&](int s, int k0) {
#pragma unroll
        for (int i = 0; i < 4; ++i) {
            int chunk = i * 256 + tid;
            int tile  = chunk >> 9;        // 0 = A, 1 = B
            int cid   = chunk & 511;
            int row   = cid >> 2;
            int kc    = (cid & 3) << 3;
            const __nv_bfloat16* src =
                g_xb + ((size_t)(bN + (tile ? tj : ti) * 128 + row)) * DDIM + k0 + kc;
            __nv_bfloat16* dst = tile ? &Bs[s][row][kc] : &As[s][row][kc];
            cp_async16(dst, src);
        }
    };

    float acc[4][4][4];
#pragma unroll
    for (int a = 0; a < 4; ++a)
#pragma unroll
        for (int c = 0; c < 4; ++c)
#pragma unroll
            for (int r = 0; r < 4; ++r) acc[a][c][r] = 0.f;

    load_stage(0, 0);
    cp_commit();

    const int KITER = DDIM / BK;        // 16
    for (int kb = 0; kb < KITER; ++kb) {
        int cur = kb & 1;
        if (kb + 1 < KITER) {
            load_stage((kb + 1) & 1, (kb + 1) * BK);
            cp_commit();
            cp_wait<1>();
        } else {
            cp_wait<0>();
        }
        __syncthreads();

#pragma unroll
        for (int kk = 0; kk < BK; kk += 16) {
            uint32_t afr[4][4], bfr[4][2];
#pragma unroll
            for (int mt = 0; mt < 4; ++mt) {
                int r0 = wm * 64 + mt * 16 + g;
                afr[mt][0] = *(const uint32_t*)&As[cur][r0][kk + t2];
                afr[mt][1] = *(const uint32_t*)&As[cur][r0 + 8][kk + t2];
                afr[mt][2] = *(const uint32_t*)&As[cur][r0][kk + t2 + 8];
                afr[mt][3] = *(const uint32_t*)&As[cur][r0 + 8][kk + t2 + 8];
            }
#pragma unroll
            for (int nt = 0; nt < 4; ++nt) {
                int c0 = wn * 32 + nt * 8 + g;
                bfr[nt][0] = *(const uint32_t*)&Bs[cur][c0][kk + t2];
                bfr[nt][1] = *(const uint32_t*)&Bs[cur][c0][kk + t2 + 8];
            }
#pragma unroll
            for (int mt = 0; mt < 4; ++mt)
#pragma unroll
                for (int nt = 0; nt < 4; ++nt) {
                    asm volatile(
                        "mma.sync.aligned.m16n8k16.row.col.f32.bf16.bf16.f32 "
                        "{%0,%1,%2,%3}, {%4,%5,%6,%7}, {%8,%9}, {%0,%1,%2,%3};\n"
                        : "+f"(acc[mt][nt][0]), "+f"(acc[mt][nt][1]),
                          "+f"(acc[mt][nt][2]), "+f"(acc[mt][nt][3])
                        : "r"(afr[mt][0]), "r"(afr[mt][1]),
                          "r"(afr[mt][2]), "r"(afr[mt][3]),
                          "r"(bfr[nt][0]), "r"(bfr[nt][1]));
                }
        }
        __syncthreads();
    }

    // ---------------- epilogue ----------------
    float* outB = out + (size_t)b * NPTS * NPTS;
    const bool mirror = (ti != tj);
    const int gi0 = ti * 128, gj0 = tj * 128;

#pragma unroll
    for (int mt = 0; mt < 4; ++mt) {
        int rl = wm * 64 + mt * 16 + g;
#pragma unroll
        for (int nt = 0; nt < 4; ++nt) {
            int cl = wn * 32 + nt * 8 + t2;
            float sb0 = s_sqj[cl],     ib0 = s_invj[cl];
            float sb1 = s_sqj[cl + 1], ib1 = s_invj[cl + 1];
#pragma unroll
            for (int h = 0; h < 2; ++h) {
                int rr = rl + h * 8;
                int gi = gi0 + rr;
                int gj = gj0 + cl;
                float sa = s_sqi[rr], ia = s_invi[rr];
                float v0 = hyp_dist(acc[mt][nt][h * 2 + 0], sa, sb0, ia, ib0, gi == gj);
                float v1 = hyp_dist(acc[mt][nt][h * 2 + 1], sa, sb1, ia, ib1, gi == gj + 1);
                float2 pk; pk.x = v0; pk.y = v1;
                *(float2*)(outB + (size_t)gi * NPTS + gj) = pk;
                if (mirror) {
                    outB[(size_t)gj * NPTS + gi]       = v0;
                    outB[(size_t)(gj + 1) * NPTS + gi] = v1;
                }
            }
        }
    }
}

// -------------------------------------------------------------- launch ----
extern "C" void kernel_launch(void* const* d_in, const int* in_sizes, int n_in,
                              void* d_out, int out_size) {
    const float* emb = (const float*)d_in[0];
    float* out = (float*)d_out;

    prep_kernel<<<BATCH * NPTS, 128>>>(emb);

    dim3 grid(PAIRS, BATCH);
    gram_dist_kernel<<<grid, 256>>>(out);
}

// round 2
// speedup vs baseline: 1.2459x; 1.2459x over previous
#include <cuda_runtime.h>
#include <cuda_bf16.h>
#include <cstdint>

#define BATCH 8
#define NPTS  4096
#define DDIM  512
#define NT    32          // 4096 / 128 tiles per dim
#define PAIRS 528         // NT*(NT+1)/2
#define BK    64
#define KITER (DDIM / BK) // 8
#define STAGE_BYTES 32768 // A 16KB + B 16KB (bf16, 128 rows x 64 cols each)
#define NSTAGE 3
#define SMEM_GEMM (NSTAGE * STAGE_BYTES)   // 96 KB

// Scratch (no cudaMalloc allowed): bf16 x, per-point sq and 1/(1-sq)
__device__ __nv_bfloat16 g_xb[(size_t)BATCH * NPTS * DDIM];
__device__ float g_sq[BATCH * NPTS];
__device__ float g_inv[BATCH * NPTS];

// ---------------------------------------------------------------- prep ----
__global__ void prep_kernel(const float* __restrict__ emb) {
    int row = blockIdx.x;               // b*NPTS + n
    int tid = threadIdx.x;              // 128 threads
    const float* src = emb + (size_t)row * DDIM;

    float v[4];
    float s = 0.f;
#pragma unroll
    for (int i = 0; i < 4; ++i) {
        v[i] = src[tid + i * 128];
        s = fmaf(v[i], v[i], s);
    }
    __shared__ float red[4];
#pragma unroll
    for (int o = 16; o > 0; o >>= 1) s += __shfl_down_sync(0xffffffffu, s, o);
    if ((tid & 31) == 0) red[tid >> 5] = s;
    __syncthreads();
    float tot = red[0] + red[1] + red[2] + red[3];

    float nrm = sqrtf(tot);
    if (nrm >= 1.f) {                   // __proj (faithful; won't trigger here)
        float invn = 1.f / nrm;
        float s2 = 0.f;
#pragma unroll
        for (int i = 0; i < 4; ++i) {
            v[i] = v[i] * invn - 1e-5f;
            s2 = fmaf(v[i], v[i], s2);
        }
#pragma unroll
        for (int o = 16; o > 0; o >>= 1) s2 += __shfl_down_sync(0xffffffffu, s2, o);
        __syncthreads();
        if ((tid & 31) == 0) red[tid >> 5] = s2;
        __syncthreads();
        tot = red[0] + red[1] + red[2] + red[3];
    }

#pragma unroll
    for (int i = 0; i < 4; ++i)
        g_xb[(size_t)row * DDIM + tid + i * 128] = __float2bfloat16(v[i]);
    if (tid == 0) {
        g_sq[row]  = tot;
        g_inv[row] = 1.f / (1.f - tot);
    }
}

// ------------------------------------------------------------- helpers ----
__device__ __forceinline__ void cp_async16(uint32_t dst, const void* src) {
    asm volatile("cp.async.cg.shared.global [%0], [%1], 16;\n" :: "r"(dst), "l"(src));
}
__device__ __forceinline__ void cp_commit() {
    asm volatile("cp.async.commit_group;\n" ::);
}
template <int N>
__device__ __forceinline__ void cp_wait() {
    asm volatile("cp.async.wait_group %0;\n" :: "n"(N));
}
__device__ __forceinline__ void ldsm_x4(uint32_t& r0, uint32_t& r1,
                                        uint32_t& r2, uint32_t& r3, uint32_t a) {
    asm volatile("ldmatrix.sync.aligned.m8n8.x4.shared.b16 {%0,%1,%2,%3}, [%4];\n"
                 : "=r"(r0), "=r"(r1), "=r"(r2), "=r"(r3) : "r"(a));
}

__device__ __forceinline__ float hyp_dist(float gv, float sa, float sb,
                                          float ia, float ib, bool diag) {
    float d2 = fmaxf(sa + sb - 2.f * gv, 0.f);
    float dn;
    asm("sqrt.approx.f32 %0, %1;" : "=f"(dn) : "f"(d2));
    float t = 2.f * dn * ia * ib;           // arg = 1 + t
    float w;
    asm("sqrt.approx.f32 %0, %1;" : "=f"(w) : "f"(t * (t + 2.f)));  // sqrt(arg^2-1)
    float arg = 1.f + t + w;
    float lg;
    asm("lg2.approx.f32 %0, %1;" : "=f"(lg) : "f"(arg));
    return (t > 0.f && !diag) ? lg * 0.69314718055994531f : 0.f;
}

// ---------------------------------------------------------------- gemm ----
__global__ void __launch_bounds__(256, 2)
gram_dist_kernel(float* __restrict__ out) {
    extern __shared__ __align__(16) char smem_raw[];
    __shared__ float s_sqi[128], s_invi[128], s_sqj[128], s_invj[128];

    const int b  = blockIdx.y;
    const int bN = b * NPTS;

    // pair index -> (ti, tj), ti <= tj
    int p = blockIdx.x, ti = 0;
    while (p >= NT - ti) { p -= NT - ti; ++ti; }
    const int tj = ti + p;

    const int tid  = threadIdx.x;
    const int warp = tid >> 5;
    const int lane = tid & 31;
    const int g  = lane >> 2;           // 0..7
    const int t2 = (lane & 3) * 2;      // 0,2,4,6
    const int wm = warp & 1;            // 2 m-blocks of 64
    const int wn = warp >> 1;           // 4 n-blocks of 32

    const uint32_t smem_u32 = (uint32_t)__cvta_generic_to_shared(smem_raw);

    // per-row/col epilogue params
    if (tid < 128) {
        s_sqi[tid]  = g_sq[bN + ti * 128 + tid];
        s_invi[tid] = g_inv[bN + ti * 128 + tid];
    } else {
        int u = tid - 128;
        s_sqj[u]  = g_sq[bN + tj * 128 + u];
        s_invj[u] = g_inv[bN + tj * 128 + u];
    }

    // --- stage loader: 2048 16B chunks (A 1024, B 1024), 8 per thread ---
    // Row layout: 128 rows x 64 bf16 (128B = 8 chunks). XOR swizzle: chunk^(row&7).
    const size_t rowA_g = (size_t)(bN + ti * 128) * DDIM;
    const size_t rowB_g = (size_t)(bN + tj * 128) * DDIM;
    auto load_stage = [&](int s, int k0) {
        uint32_t sbase = smem_u32 + s * STAGE_BYTES;
#pragma unroll
        for (int i = 0; i < 8; ++i) {
            int chunk = i * 256 + tid;
            int tile  = chunk >> 10;       // 0 = A, 1 = B
            int cid   = chunk & 1023;
            int row   = cid >> 3;
            int c     = cid & 7;
            const __nv_bfloat16* src =
                g_xb + (tile ? rowB_g : rowA_g) + (size_t)row * DDIM + k0 + c * 8;
            uint32_t dst = sbase + tile * 16384 + row * 128 + ((c ^ (row & 7)) << 4);
            cp_async16(dst, src);
        }
    };

    // per-thread ldmatrix geometry (XOR term identical for A and B: lane&7)
    const int swz = lane & 7;
    const int dcA = lane >> 4;                              // 0/1
    const int dcB = (lane >> 3) & 1;                        // 0/1
    uint32_t aByte[4], bByte[2];
#pragma unroll
    for (int mt = 0; mt < 4; ++mt)
        aByte[mt] = (uint32_t)((wm * 64 + mt * 16 + (lane & 15)) * 128);
#pragma unroll
    for (int pp = 0; pp < 2; ++pp)
        bByte[pp] = (uint32_t)(16384 + (wn * 32 + pp * 16 + (lane & 7) + ((lane >> 4) << 3)) * 128);

    float acc[4][4][4];
#pragma unroll
    for (int a = 0; a < 4; ++a)
#pragma unroll
        for (int c = 0; c < 4; ++c)
#pragma unroll
            for (int r = 0; r < 4; ++r) acc[a][c][r] = 0.f;

    load_stage(0, 0); cp_commit();
    load_stage(1, BK); cp_commit();

    for (int kb = 0; kb < KITER; ++kb) {
        if (kb + 2 < KITER) cp_wait<1>(); else cp_wait<0>();
        __syncthreads();
        if (kb + 2 < KITER) { load_stage((kb + 2) % NSTAGE, (kb + 2) * BK); cp_commit(); }

        uint32_t sbase = smem_u32 + (kb % NSTAGE) * STAGE_BYTES;
#pragma unroll
        for (int kk = 0; kk < BK; kk += 16) {
            const int c0 = kk >> 3;                          // 0,2,4,6
            const uint32_t cA = (uint32_t)(((c0 | dcA) ^ swz) << 4);
            const uint32_t cB = (uint32_t)(((c0 | dcB) ^ swz) << 4);
            uint32_t afr[4][4], bfr[4][2];
#pragma unroll
            for (int mt = 0; mt < 4; ++mt)
                ldsm_x4(afr[mt][0], afr[mt][1], afr[mt][2], afr[mt][3],
                        sbase + aByte[mt] + cA);
#pragma unroll
            for (int pp = 0; pp < 2; ++pp)
                ldsm_x4(bfr[2 * pp][0], bfr[2 * pp][1], bfr[2 * pp + 1][0], bfr[2 * pp + 1][1],
                        sbase + bByte[pp] + cB);
#pragma unroll
            for (int mt = 0; mt < 4; ++mt)
#pragma unroll
                for (int nt = 0; nt < 4; ++nt) {
                    asm volatile(
                        "mma.sync.aligned.m16n8k16.row.col.f32.bf16.bf16.f32 "
                        "{%0,%1,%2,%3}, {%4,%5,%6,%7}, {%8,%9}, {%0,%1,%2,%3};\n"
                        : "+f"(acc[mt][nt][0]), "+f"(acc[mt][nt][1]),
                          "+f"(acc[mt][nt][2]), "+f"(acc[mt][nt][3])
                        : "r"(afr[mt][0]), "r"(afr[mt][1]),
                          "r"(afr[mt][2]), "r"(afr[mt][3]),
                          "r"(bfr[nt][0]), "r"(bfr[nt][1]));
                }
        }
    }

    // ---------------- epilogue ----------------
    float* outB = out + (size_t)b * NPTS * NPTS;
    const bool mirror = (ti != tj);
    const int gi0 = ti * 128, gj0 = tj * 128;

    // 1) distances in place + direct (row-major) stores
#pragma unroll
    for (int mt = 0; mt < 4; ++mt) {
        int rl = wm * 64 + mt * 16 + g;
#pragma unroll
        for (int nt = 0; nt < 4; ++nt) {
            int cl = wn * 32 + nt * 8 + t2;
            float sb0 = s_sqj[cl],     ib0 = s_invj[cl];
            float sb1 = s_sqj[cl + 1], ib1 = s_invj[cl + 1];
#pragma unroll
            for (int h = 0; h < 2; ++h) {
                int rr = rl + h * 8;
                int gi = gi0 + rr;
                int gj = gj0 + cl;
                float sa = s_sqi[rr], ia = s_invi[rr];
                float v0 = hyp_dist(acc[mt][nt][h * 2 + 0], sa, sb0, ia, ib0, gi == gj);
                float v1 = hyp_dist(acc[mt][nt][h * 2 + 1], sa, sb1, ia, ib1, gi == gj + 1);
                acc[mt][nt][h * 2 + 0] = v0;
                acc[mt][nt][h * 2 + 1] = v1;
                float2 pk; pk.x = v0; pk.y = v1;
                *(float2*)(outB + (size_t)gi * NPTS + gj) = pk;
            }
        }
    }

    // 2) mirror (transposed) stores via smem staging, 32 j-rows at a time.
    //    stageT[c][r]: stride 132 floats -> bank = (4c + r) & 31, conflict-free.
    __syncthreads();                    // gemm smem reads fully done
    float* stageT = (float*)smem_raw;   // 32 * 132 * 4B = 16.9 KB
    for (int jc = 0; jc < 4; ++jc) {
        if (mirror && wn == jc) {
#pragma unroll
            for (int mt = 0; mt < 4; ++mt) {
#pragma unroll
                for (int nt = 0; nt < 4; ++nt) {
                    int c = nt * 8 + t2;
#pragma unroll
                    for (int h = 0; h < 2; ++h) {
                        int r = wm * 64 + mt * 16 + g + h * 8;
                        stageT[c * 132 + r]       = acc[mt][nt][h * 2 + 0];
                        stageT[(c + 1) * 132 + r] = acc[mt][nt][h * 2 + 1];
                    }
                }
            }
        }
        __syncthreads();
        if (mirror) {
            // 32 rows x 128 floats = 1024 float4, 256 threads x 4
#pragma unroll
            for (int it = 0; it < 4; ++it) {
                int idx = it * 256 + tid;
                int row = idx >> 5;          // 0..31
                int q   = idx & 31;          // float4 index within row
                float4 v = *(const float4*)&stageT[row * 132 + q * 4];
                *(float4*)(outB + (size_t)(gj0 + jc * 32 + row) * NPTS + gi0 + q * 4) = v;
            }
        }
        __syncthreads();
    }
}

// -------------------------------------------------------------- launch ----
extern "C" void kernel_launch(void* const* d_in, const int* in_sizes, int n_in,
                              void* d_out, int out_size) {
    const float* emb = (const float*)d_in[0];
    float* out = (float*)d_out;

    prep_kernel<<<BATCH * NPTS, 128>>>(emb);

    cudaFuncSetAttribute(gram_dist_kernel,
                         cudaFuncAttributeMaxDynamicSharedMemorySize, SMEM_GEMM);
    dim3 grid(PAIRS, BATCH);
    gram_dist_kernel<<<grid, 256, SMEM_GEMM>>>(out);
}